// round 16
// baseline (speedup 1.0000x reference)
#include <cuda_runtime.h>

#define NN 4096
#define MM 32
#define LOG2F_ 0.693147180559945f

typedef unsigned long long u64;

// ---- scratch globals ----
__device__ float g_pre[NN * 256];  // ielin(feat) per node
__device__ float g_acc[NN * 704];  // coupling accumulators
__device__ float g_agg[NN * 256];  // post-w_a aggregate, GATED

__device__ __forceinline__ float ssp(float x) {
    return fmaxf(x, 0.f) + __logf(1.f + __expf(-fabsf(x))) - LOG2F_;
}
__device__ __forceinline__ u64 pk2(float a, float b) {
    u64 r; asm("mov.b64 %0, {%1, %2};" : "=l"(r) : "f"(a), "f"(b)); return r;
}
__device__ __forceinline__ void upk2(u64 v, float& a, float& b) {
    asm("mov.b64 {%0, %1}, %2;" : "=f"(a), "=f"(b) : "l"(v));
}
__device__ __forceinline__ u64 fma2_(u64 a, u64 b, u64 c) {
    u64 r; asm("fma.rn.f32x2 %0, %1, %2, %3;" : "=l"(r) : "l"(a), "l"(b), "l"(c)); return r;
}

// ============================================================
// K1: g_pre = ielin(feat, wp0, wp1). 8 nodes/block (32 rows), grid 512.
// ============================================================
#define KP_SMEM ((4096 + 4096 + 64 * 36) * 4)
__global__ void __launch_bounds__(256) k_pre(const float* __restrict__ feat,
                                             const float* __restrict__ wp0,
                                             const float* __restrict__ wp1) {
    extern __shared__ float sm[];
    float* sW0 = sm;
    float* sW1 = sm + 4096;
    float* sAt = sm + 8192;  // [k64][row32], stride 36
    int t = threadIdx.x;
    for (int i = t; i < 1024; i += 256) {
        ((float4*)sW0)[i] = ((const float4*)wp0)[i];
        ((float4*)sW1)[i] = ((const float4*)wp1)[i];
    }
    const float4* src = (const float4*)feat + blockIdx.x * 512;
#pragma unroll
    for (int jj = 0; jj < 2; jj++) {
        int idx = t + jj * 256;
        float4 v = src[idx];
        int d = idx * 4, r = d >> 6, k0 = d & 63;
        sAt[(k0 + 0) * 36 + r] = v.x;
        sAt[(k0 + 1) * 36 + r] = v.y;
        sAt[(k0 + 2) * 36 + r] = v.z;
        sAt[(k0 + 3) * 36 + r] = v.w;
    }
    __syncthreads();
    int rg = t >> 5, c0 = (t & 31) * 2;
    u64 acc0 = pk2(0.f, 0.f), acc1 = acc0, acc2 = acc0, acc3 = acc0;
#pragma unroll 4
    for (int k = 0; k < 64; k++) {
        float4 a = *(const float4*)(sAt + k * 36 + rg * 4);
        u64 w0 = *(const u64*)(sW0 + k * 64 + c0);
        u64 w1 = *(const u64*)(sW1 + k * 64 + c0);
        acc0 = fma2_(pk2(a.x, a.x), w0, acc0);
        acc1 = fma2_(pk2(a.y, a.y), w1, acc1);
        acc2 = fma2_(pk2(a.z, a.z), w1, acc2);
        acc3 = fma2_(pk2(a.w, a.w), w1, acc3);
    }
    int node = blockIdx.x * 8 + rg;
    *(u64*)(g_pre + node * 256 + c0) = acc0;
    *(u64*)(g_pre + node * 256 + 64 + c0) = acc1;
    *(u64*)(g_pre + node * 256 + 128 + c0) = acc2;
    *(u64*)(g_pre + node * 256 + 192 + c0) = acc3;
#if __CUDA_ARCH__ >= 900
    cudaTriggerProgrammaticLaunchCompletion();
#endif
}

// ============================================================
// K2: fused edge kernel (filters + coupling). warp = node.
//     4 warps/block (128 thr), grid 1024 (R15 proven shape).
// ============================================================
#define KE_WARPS 4
#define KE_PW (576 + 272 + 128)  // sRB[16][36] + sH[4][68] + s_u[32]f4
#define KE_SMEM ((1024 + 4096 + KE_WARPS * KE_PW) * 4)

#define COUPLE(UE, A0, AY, AZ, AX, F) do { \
    float fa, fb; upk2(F, fa, fb); \
    float uy = UE.x, uz = UE.y, ux = UE.z; \
    float sa = AY.x * uy + AZ.x * uz + AX.x * ux; \
    float sb = AY.y * uy + AZ.y * uz + AX.y * ux; \
    float t0a = A0.x * fa, t0b = A0.y * fb; \
    S0a += t0a;       S0b += t0b; \
    S1a += sa * fa;   S1b += sb * fb; \
    U0a += uy * t0a;  U0b += uy * t0b; \
    U1a += uz * t0a;  U1b += uz * t0b; \
    U2a += ux * t0a;  U2b += ux * t0b; \
    P0a += AY.x * fa; P0b += AY.y * fb; \
    P1a += AZ.x * fa; P1b += AZ.y * fb; \
    P2a += AX.x * fa; P2b += AX.y * fb; \
    float cya = AZ.x * ux - AX.x * uz, cyb = AZ.y * ux - AX.y * uz; \
    float cza = AX.x * uy - AY.x * ux, czb = AX.y * uy - AY.y * ux; \
    float cxa = AY.x * uz - AZ.x * uy, cxb = AY.y * uz - AZ.y * uy; \
    Q0a += cya * fa;  Q0b += cyb * fb; \
    Q1a += cza * fa;  Q1b += czb * fb; \
    Q2a += cxa * fa;  Q2b += cxb * fb; \
} while (0)

__global__ void __launch_bounds__(128) k_edge(const float* __restrict__ xyz,
                                              const float* __restrict__ wf1,
                                              const float* __restrict__ wf2,
                                              const int* __restrict__ src,
                                              const int* __restrict__ emask) {
    extern __shared__ float sm[];
    float* sW1 = sm;         // wf1 [16][64]
    float* sW2 = sm + 1024;  // wf2 [64][64]
    int t = threadIdx.x, w = t >> 5, lane = t & 31;
    for (int i = t; i < 256; i += 128) ((float4*)sW1)[i] = ((const float4*)wf1)[i];
    for (int i = t; i < 1024; i += 128) ((float4*)sW2)[i] = ((const float4*)wf2)[i];
    float* base = sm + 5120 + w * KE_PW;
    float* sRB = base;                   // [q16][36]
    float* sH = base + 576;              // [e4][68]
    float4* s_u = (float4*)(base + 848); // [32] (uy,uz,ux,j)
    __syncthreads();

    int node = blockIdx.x * KE_WARPS + w;
    // ---- phase A: lane = edge (inputs only; overlaps with k_pre via PDL) ----
    s_u[lane] = make_float4(0.f, 0.f, 0.f, __int_as_float(node));
    __syncwarp();
    int eid = node * MM + lane;
    int mk = emask[eid];
    int j = src[eid];
    float nx = xyz[node * 3], ny = xyz[node * 3 + 1], nz = xyz[node * 3 + 2];
    float rx = xyz[j * 3] - nx, ry = xyz[j * 3 + 1] - ny, rz = xyz[j * 3 + 2] - nz;
    float d2 = rx * rx + ry * ry + rz * rz;
    float invd = rsqrtf(d2);
    float x = d2 * invd * 0.2f;
    bool act = (mk != 0) && (x < 1.f);
    unsigned actmask = __ballot_sync(0xffffffffu, act);
    int nact = __popc(actmask);
    int rank = __popc(actmask & ((1u << lane) - 1u));
    if (act) {
        float x3 = x * x * x;
        float env = 1.f + x3 * (-10.f + x * (15.f - 6.f * x));
        float scale = env * invd;
        s_u[rank] = make_float4(ry * invd, rz * invd, rx * invd, __int_as_float(j));
#pragma unroll
        for (int q = 0; q < 16; q++) sRB[q * 36 + rank] = __sinf(x * (float)q) * scale;
    }
    __syncwarp();

#if __CUDA_ARCH__ >= 900
    cudaGridDependencySynchronize();   // g_pre must be complete past this point
#endif

    // ---- phase B: 4-edge tiles; lane = channel pair c0 ----
    int c0 = lane * 2;
    float S0a = 0, S0b = 0, S1a = 0, S1b = 0;
    float U0a = 0, U0b = 0, U1a = 0, U1b = 0, U2a = 0, U2b = 0;
    float P0a = 0, P0b = 0, P1a = 0, P1b = 0, P2a = 0, P2b = 0;
    float Q0a = 0, Q0b = 0, Q1a = 0, Q1b = 0, Q2a = 0, Q2b = 0;

    for (int r0 = 0; r0 < nact; r0 += 4) {
        float4 ue0 = s_u[r0], ue1 = s_u[r0 + 1], ue2 = s_u[r0 + 2], ue3 = s_u[r0 + 3];
        const float* p0 = g_pre + __float_as_int(ue0.w) * 256 + c0;
        const float* p1 = g_pre + __float_as_int(ue1.w) * 256 + c0;
        const float* p2 = g_pre + __float_as_int(ue2.w) * 256 + c0;
        const float* p3 = g_pre + __float_as_int(ue3.w) * 256 + c0;
        float2 A00 = *(const float2*)(p0), A0y = *(const float2*)(p0 + 64),
               A0z = *(const float2*)(p0 + 128), A0x = *(const float2*)(p0 + 192);
        float2 B00 = *(const float2*)(p1), B0y = *(const float2*)(p1 + 64),
               B0z = *(const float2*)(p1 + 128), B0x = *(const float2*)(p1 + 192);
        float2 C00 = *(const float2*)(p2), C0y = *(const float2*)(p2 + 64),
               C0z = *(const float2*)(p2 + 128), C0x = *(const float2*)(p2 + 192);
        float2 D00 = *(const float2*)(p3), D0y = *(const float2*)(p3 + 64),
               D0z = *(const float2*)(p3 + 128), D0x = *(const float2*)(p3 + 192);

        u64 H0 = pk2(0.f, 0.f), H1 = H0, H2 = H0, H3 = H0;
#pragma unroll
        for (int q = 0; q < 16; q++) {
            float4 rb = *(const float4*)(sRB + q * 36 + r0);
            u64 wv = *(const u64*)(sW1 + q * 64 + c0);
            H0 = fma2_(pk2(rb.x, rb.x), wv, H0);
            H1 = fma2_(pk2(rb.y, rb.y), wv, H1);
            H2 = fma2_(pk2(rb.z, rb.z), wv, H2);
            H3 = fma2_(pk2(rb.w, rb.w), wv, H3);
        }
        {
            float a, b;
            upk2(H0, a, b); *(u64*)(sH + 0 * 68 + c0) = pk2(ssp(a), ssp(b));
            upk2(H1, a, b); *(u64*)(sH + 1 * 68 + c0) = pk2(ssp(a), ssp(b));
            upk2(H2, a, b); *(u64*)(sH + 2 * 68 + c0) = pk2(ssp(a), ssp(b));
            upk2(H3, a, b); *(u64*)(sH + 3 * 68 + c0) = pk2(ssp(a), ssp(b));
        }
        __syncwarp();

        u64 F0 = pk2(0.f, 0.f), F1 = F0, F2 = F0, F3 = F0;
#pragma unroll 4
        for (int kk = 0; kk < 64; kk += 4) {
            float4 h0 = *(const float4*)(sH + 0 * 68 + kk);
            float4 h1 = *(const float4*)(sH + 1 * 68 + kk);
            float4 h2 = *(const float4*)(sH + 2 * 68 + kk);
            float4 h3 = *(const float4*)(sH + 3 * 68 + kk);
            u64 w0 = *(const u64*)(sW2 + (kk + 0) * 64 + c0);
            u64 w1 = *(const u64*)(sW2 + (kk + 1) * 64 + c0);
            u64 w2 = *(const u64*)(sW2 + (kk + 2) * 64 + c0);
            u64 w3 = *(const u64*)(sW2 + (kk + 3) * 64 + c0);
            F0 = fma2_(pk2(h0.x, h0.x), w0, F0);
            F1 = fma2_(pk2(h1.x, h1.x), w0, F1);
            F2 = fma2_(pk2(h2.x, h2.x), w0, F2);
            F3 = fma2_(pk2(h3.x, h3.x), w0, F3);
            F0 = fma2_(pk2(h0.y, h0.y), w1, F0);
            F1 = fma2_(pk2(h1.y, h1.y), w1, F1);
            F2 = fma2_(pk2(h2.y, h2.y), w1, F2);
            F3 = fma2_(pk2(h3.y, h3.y), w1, F3);
            F0 = fma2_(pk2(h0.z, h0.z), w2, F0);
            F1 = fma2_(pk2(h1.z, h1.z), w2, F1);
            F2 = fma2_(pk2(h2.z, h2.z), w2, F2);
            F3 = fma2_(pk2(h3.z, h3.z), w2, F3);
            F0 = fma2_(pk2(h0.w, h0.w), w3, F0);
            F1 = fma2_(pk2(h1.w, h1.w), w3, F1);
            F2 = fma2_(pk2(h2.w, h2.w), w3, F2);
            F3 = fma2_(pk2(h3.w, h3.w), w3, F3);
        }
        if (r0 + 1 >= nact) F1 = pk2(0.f, 0.f);
        if (r0 + 2 >= nact) F2 = pk2(0.f, 0.f);
        if (r0 + 3 >= nact) F3 = pk2(0.f, 0.f);

        COUPLE(ue0, A00, A0y, A0z, A0x, F0);
        COUPLE(ue1, B00, B0y, B0z, B0x, F1);
        COUPLE(ue2, C00, C0y, C0z, C0x, F2);
        COUPLE(ue3, D00, D0y, D0z, D0x, F3);
        __syncwarp();
    }

    float* dst = g_acc + node * 704 + c0;
    *(float2*)(dst + 0)   = make_float2(S0a, S0b);
    *(float2*)(dst + 64)  = make_float2(S1a, S1b);
    *(float2*)(dst + 128) = make_float2(U0a, U0b);
    *(float2*)(dst + 192) = make_float2(U1a, U1b);
    *(float2*)(dst + 256) = make_float2(U2a, U2b);
    *(float2*)(dst + 320) = make_float2(P0a, P0b);
    *(float2*)(dst + 384) = make_float2(P1a, P1b);
    *(float2*)(dst + 448) = make_float2(P2a, P2b);
    *(float2*)(dst + 512) = make_float2(Q0a, Q0b);
    *(float2*)(dst + 576) = make_float2(Q1a, Q1b);
    *(float2*)(dst + 640) = make_float2(Q2a, Q2b);
#if __CUDA_ARCH__ >= 900
    cudaTriggerProgrammaticLaunchCompletion();
#endif
}

// ============================================================
// K3: combined w_a GEMMs + FUSED GATE. g_agg stores gated values.
//   l0 blocks: a0*ssp(a0). l1 blocks: warp holds all 3 m-components
//   of its nodes -> gate1 = ssp(||a1||) computed in registers.
// ============================================================
#define KAG_SMEM (12288 * 4)
__global__ void __launch_bounds__(256) k_ag(const float* __restrict__ wa0,
                                            const float* __restrict__ wa1) {
    extern __shared__ float sW[];
    int t = threadIdx.x, w = t >> 5, c0 = (t & 31) * 2;
    if (blockIdx.x < 256) {
        for (int i = t; i < 2048; i += 256) ((float4*)sW)[i] = ((const float4*)wa0)[i];
#if __CUDA_ARCH__ >= 900
        cudaGridDependencySynchronize();
#endif
        __syncthreads();
        int n0 = blockIdx.x * 16 + w * 2;
        const float* A = g_acc + n0 * 704;
        const float* B = A + 704;
        u64 e0 = pk2(0.f, 0.f), e1 = e0, f0 = e0, f1 = e0;
#pragma unroll 4
        for (int kk = 0; kk < 64; kk += 4) {
            float4 a = *(const float4*)(A + kk);
            float4 a2 = *(const float4*)(A + 64 + kk);
            float4 b = *(const float4*)(B + kk);
            float4 b2 = *(const float4*)(B + 64 + kk);
            u64 w0 = *(const u64*)(sW + (kk + 0) * 64 + c0);
            u64 v0 = *(const u64*)(sW + (64 + kk + 0) * 64 + c0);
            u64 w1 = *(const u64*)(sW + (kk + 1) * 64 + c0);
            u64 v1 = *(const u64*)(sW + (64 + kk + 1) * 64 + c0);
            u64 w2 = *(const u64*)(sW + (kk + 2) * 64 + c0);
            u64 v2 = *(const u64*)(sW + (64 + kk + 2) * 64 + c0);
            u64 w3 = *(const u64*)(sW + (kk + 3) * 64 + c0);
            u64 v3 = *(const u64*)(sW + (64 + kk + 3) * 64 + c0);
            e0 = fma2_(pk2(a.x, a.x), w0, e0);
            f0 = fma2_(pk2(b.x, b.x), w0, f0);
            e1 = fma2_(pk2(a2.x, a2.x), v0, e1);
            f1 = fma2_(pk2(b2.x, b2.x), v0, f1);
            e0 = fma2_(pk2(a.y, a.y), w1, e0);
            f0 = fma2_(pk2(b.y, b.y), w1, f0);
            e1 = fma2_(pk2(a2.y, a2.y), v1, e1);
            f1 = fma2_(pk2(b2.y, b2.y), v1, f1);
            e0 = fma2_(pk2(a.z, a.z), w2, e0);
            f0 = fma2_(pk2(b.z, b.z), w2, f0);
            e1 = fma2_(pk2(a2.z, a2.z), v2, e1);
            f1 = fma2_(pk2(b2.z, b2.z), v2, f1);
            e0 = fma2_(pk2(a.w, a.w), w3, e0);
            f0 = fma2_(pk2(b.w, b.w), w3, f0);
            e1 = fma2_(pk2(a2.w, a2.w), v3, e1);
            f1 = fma2_(pk2(b2.w, b2.w), v3, f1);
        }
        float xa, xb, ya, yb;
        upk2(e0, xa, xb); upk2(e1, ya, yb);
        float s0 = xa + ya, s1 = xb + yb;
        *(float2*)(g_agg + n0 * 256 + c0) = make_float2(s0 * ssp(s0), s1 * ssp(s1));
        upk2(f0, xa, xb); upk2(f1, ya, yb);
        s0 = xa + ya; s1 = xb + yb;
        *(float2*)(g_agg + (n0 + 1) * 256 + c0) = make_float2(s0 * ssp(s0), s1 * ssp(s1));
    } else {
        for (int i = t; i < 3072; i += 256) ((float4*)sW)[i] = ((const float4*)wa1)[i];
#if __CUDA_ARCH__ >= 900
        cudaGridDependencySynchronize();
#endif
        __syncthreads();
        int n0 = (blockIdx.x - 256) * 16 + w * 2;
        u64 m0 = pk2(0.f, 0.f), m1 = m0, m2 = m0;
        u64 q0 = m0, q1 = m0, q2 = m0;
#pragma unroll
        for (int s = 0; s < 3; s++) {
            const float* As = g_acc + n0 * 704 + 128 + s * 192;
            const float* Bs = As + 704;
            const float* ws = sW + s * 4096;
#pragma unroll 2
            for (int kk = 0; kk < 64; kk += 4) {
                float4 a0 = *(const float4*)(As + kk);
                float4 a1 = *(const float4*)(As + 64 + kk);
                float4 a2 = *(const float4*)(As + 128 + kk);
                float4 b0 = *(const float4*)(Bs + kk);
                float4 b1 = *(const float4*)(Bs + 64 + kk);
                float4 b2 = *(const float4*)(Bs + 128 + kk);
                u64 w0 = *(const u64*)(ws + (kk + 0) * 64 + c0);
                u64 w1 = *(const u64*)(ws + (kk + 1) * 64 + c0);
                u64 w2 = *(const u64*)(ws + (kk + 2) * 64 + c0);
                u64 w3 = *(const u64*)(ws + (kk + 3) * 64 + c0);
                m0 = fma2_(pk2(a0.x, a0.x), w0, m0);
                q0 = fma2_(pk2(b0.x, b0.x), w0, q0);
                m1 = fma2_(pk2(a1.x, a1.x), w0, m1);
                q1 = fma2_(pk2(b1.x, b1.x), w0, q1);
                m2 = fma2_(pk2(a2.x, a2.x), w0, m2);
                q2 = fma2_(pk2(b2.x, b2.x), w0, q2);
                m0 = fma2_(pk2(a0.y, a0.y), w1, m0);
                q0 = fma2_(pk2(b0.y, b0.y), w1, q0);
                m1 = fma2_(pk2(a1.y, a1.y), w1, m1);
                q1 = fma2_(pk2(b1.y, b1.y), w1, q1);
                m2 = fma2_(pk2(a2.y, a2.y), w1, m2);
                q2 = fma2_(pk2(b2.y, b2.y), w1, q2);
                m0 = fma2_(pk2(a0.z, a0.z), w2, m0);
                q0 = fma2_(pk2(b0.z, b0.z), w2, q0);
                m1 = fma2_(pk2(a1.z, a1.z), w2, m1);
                q1 = fma2_(pk2(b1.z, b1.z), w2, q1);
                m2 = fma2_(pk2(a2.z, a2.z), w2, m2);
                q2 = fma2_(pk2(b2.z, b2.z), w2, q2);
                m0 = fma2_(pk2(a0.w, a0.w), w3, m0);
                q0 = fma2_(pk2(b0.w, b0.w), w3, q0);
                m1 = fma2_(pk2(a1.w, a1.w), w3, m1);
                q1 = fma2_(pk2(b1.w, b1.w), w3, q1);
                m2 = fma2_(pk2(a2.w, a2.w), w3, m2);
                q2 = fma2_(pk2(b2.w, b2.w), w3, q2);
            }
        }
        // gate l1 in registers: gt1 = ssp(||(m0,m1,m2)||)
        {
            float m0a, m0b, m1a, m1b, m2a, m2b;
            upk2(m0, m0a, m0b); upk2(m1, m1a, m1b); upk2(m2, m2a, m2b);
            float ga = ssp(sqrtf(m0a * m0a + m1a * m1a + m2a * m2a + 1e-12f));
            float gb = ssp(sqrtf(m0b * m0b + m1b * m1b + m2b * m2b + 1e-12f));
            *(float2*)(g_agg + n0 * 256 + 64 + c0) = make_float2(m0a * ga, m0b * gb);
            *(float2*)(g_agg + n0 * 256 + 128 + c0) = make_float2(m1a * ga, m1b * gb);
            *(float2*)(g_agg + n0 * 256 + 192 + c0) = make_float2(m2a * ga, m2b * gb);
        }
        {
            float m0a, m0b, m1a, m1b, m2a, m2b;
            upk2(q0, m0a, m0b); upk2(q1, m1a, m1b); upk2(q2, m2a, m2b);
            float ga = ssp(sqrtf(m0a * m0a + m1a * m1a + m2a * m2a + 1e-12f));
            float gb = ssp(sqrtf(m0b * m0b + m1b * m1b + m2b * m2b + 1e-12f));
            *(float2*)(g_agg + (n0 + 1) * 256 + 64 + c0) = make_float2(m0a * ga, m0b * gb);
            *(float2*)(g_agg + (n0 + 1) * 256 + 128 + c0) = make_float2(m1a * ga, m1b * gb);
            *(float2*)(g_agg + (n0 + 1) * 256 + 192 + c0) = make_float2(m2a * ga, m2b * gb);
        }
    }
#if __CUDA_ARCH__ >= 900
    cudaTriggerProgrammaticLaunchCompletion();
#endif
}

// ============================================================
// K4: w_b ielin + residual on pre-gated g_agg. 8 nodes/block, grid 512.
//     Gate phase removed; direct transpose-load into sAt.
// ============================================================
#define KFN_SMEM ((4096 + 4096 + 64 * 36) * 4)
__global__ void __launch_bounds__(256) k_fin(const float* __restrict__ feat,
                                             const float* __restrict__ wb0,
                                             const float* __restrict__ wb1,
                                             float* __restrict__ out) {
    extern __shared__ float sm[];
    float* sW0 = sm;
    float* sW1 = sm + 4096;
    float* sAt = sm + 8192;   // gated transposed [k64][row32], stride 36
    int t = threadIdx.x;
    for (int i = t; i < 1024; i += 256) {
        ((float4*)sW0)[i] = ((const float4*)wb0)[i];
        ((float4*)sW1)[i] = ((const float4*)wb1)[i];
    }
#if __CUDA_ARCH__ >= 900
    cudaGridDependencySynchronize();   // g_agg ready past this point
#endif
    int nodeBase = blockIdx.x * 8;
    for (int i = t; i < 512; i += 256) {
        float4 v = *((const float4*)(g_agg + nodeBase * 256) + i);
        int d = i * 4;
        int nl = d >> 8;          // local node 0..7
        int rem = d & 255;
        int g = rem >> 6;         // irrep row group 0..3
        int c = rem & 63;         // channel (k index)
        int row = nl * 4 + g;
        sAt[(c + 0) * 36 + row] = v.x;
        sAt[(c + 1) * 36 + row] = v.y;
        sAt[(c + 2) * 36 + row] = v.z;
        sAt[(c + 3) * 36 + row] = v.w;
    }
    __syncthreads();
    int rg = t >> 5, c0 = (t & 31) * 2;
    u64 acc0 = pk2(0.f, 0.f), acc1 = acc0, acc2 = acc0, acc3 = acc0;
#pragma unroll 4
    for (int k = 0; k < 64; k++) {
        float4 a = *(const float4*)(sAt + k * 36 + rg * 4);
        u64 w0 = *(const u64*)(sW0 + k * 64 + c0);
        u64 w1 = *(const u64*)(sW1 + k * 64 + c0);
        acc0 = fma2_(pk2(a.x, a.x), w0, acc0);
        acc1 = fma2_(pk2(a.y, a.y), w1, acc1);
        acc2 = fma2_(pk2(a.z, a.z), w1, acc2);
        acc3 = fma2_(pk2(a.w, a.w), w1, acc3);
    }
    int node = nodeBase + rg;
    u64 av[4] = {acc0, acc1, acc2, acc3};
#pragma unroll
    for (int jj = 0; jj < 4; jj++) {
        int idx = node * 256 + jj * 64 + c0;
        float2 fv = *(const float2*)(feat + idx);
        float oa, ob;
        upk2(av[jj], oa, ob);
        *(float2*)(out + idx) = make_float2(fv.x + oa, fv.y + ob);
    }
}

// ============================================================
template <typename... Args>
static void launch_pdl(void (*kern)(Args...), int grid, int block, int smem, Args... args) {
    cudaLaunchConfig_t cfg = {};
    cfg.gridDim = dim3(grid, 1, 1);
    cfg.blockDim = dim3(block, 1, 1);
    cfg.dynamicSmemBytes = (size_t)smem;
    cfg.stream = 0;
    cudaLaunchAttribute attr[1];
    attr[0].id = cudaLaunchAttributeProgrammaticStreamSerialization;
    attr[0].val.programmaticStreamSerializationAllowed = 1;
    cfg.attrs = attr;
    cfg.numAttrs = 1;
    cudaLaunchKernelEx(&cfg, kern, args...);
}

extern "C" void kernel_launch(void* const* d_in, const int* in_sizes, int n_in,
                              void* d_out, int out_size) {
    const float* xyz = (const float*)d_in[0];
    const float* feat = (const float*)d_in[1];
    const float* wf1 = (const float*)d_in[2];
    const float* wf2 = (const float*)d_in[3];
    const float* wp0 = (const float*)d_in[4];
    const float* wp1 = (const float*)d_in[5];
    const float* wa0 = (const float*)d_in[6];
    const float* wa1 = (const float*)d_in[7];
    const float* wb0 = (const float*)d_in[8];
    const float* wb1 = (const float*)d_in[9];
    const int* src = (const int*)d_in[10];
    const int* emask = (const int*)d_in[11];
    float* out = (float*)d_out;

    cudaFuncSetAttribute(k_pre, cudaFuncAttributeMaxDynamicSharedMemorySize, KP_SMEM);
    cudaFuncSetAttribute(k_edge, cudaFuncAttributeMaxDynamicSharedMemorySize, KE_SMEM);
    cudaFuncSetAttribute(k_ag, cudaFuncAttributeMaxDynamicSharedMemorySize, KAG_SMEM);
    cudaFuncSetAttribute(k_fin, cudaFuncAttributeMaxDynamicSharedMemorySize, KFN_SMEM);

    k_pre<<<512, 256, KP_SMEM>>>(feat, wp0, wp1);
    launch_pdl(k_edge, NN / KE_WARPS, 128, KE_SMEM, xyz, wf1, wf2, src, emask);
    launch_pdl(k_ag, 512, 256, KAG_SMEM, wa0, wa1);
    launch_pdl(k_fin, 512, 256, KFN_SMEM, feat, wb0, wb1, out);
}

// round 17
// speedup vs baseline: 1.0338x; 1.0338x over previous
#include <cuda_runtime.h>

#define NN 4096
#define MM 32
#define LOG2F_ 0.693147180559945f

typedef unsigned long long u64;

// ---- scratch globals ----
__device__ float g_pre[NN * 256];  // ielin(feat) per node
__device__ float g_acc[NN * 704];  // coupling accumulators
__device__ float g_agg[NN * 256];  // post-w_a aggregate, GATED

__device__ __forceinline__ float ssp(float x) {
    return fmaxf(x, 0.f) + __logf(1.f + __expf(-fabsf(x))) - LOG2F_;
}
__device__ __forceinline__ u64 pk2(float a, float b) {
    u64 r; asm("mov.b64 %0, {%1, %2};" : "=l"(r) : "f"(a), "f"(b)); return r;
}
__device__ __forceinline__ void upk2(u64 v, float& a, float& b) {
    asm("mov.b64 {%0, %1}, %2;" : "=f"(a), "=f"(b) : "l"(v));
}
__device__ __forceinline__ u64 fma2_(u64 a, u64 b, u64 c) {
    u64 r; asm("fma.rn.f32x2 %0, %1, %2, %3;" : "=l"(r) : "l"(a), "l"(b), "l"(c)); return r;
}

// ============================================================
// K1: g_pre = ielin(feat, wp0, wp1). 16 nodes/block (64 rows), 128 thr,
//     grid 256. Warp = 16 rows x 64 cols: 8 smem wavefronts per 1024 MACs
//     (smem-BW : FMA = 1:1, the balanced point).
// ============================================================
#define KP_SMEM ((8192 + 64 * 68) * 4)
__global__ void __launch_bounds__(128) k_pre(const float* __restrict__ feat,
                                             const float* __restrict__ wp0,
                                             const float* __restrict__ wp1) {
    extern __shared__ float sm[];
    float* sW0 = sm;
    float* sW1 = sm + 4096;
    float* sAt = sm + 8192;  // [k64][row64], stride 68
    int t = threadIdx.x;
    for (int i = t; i < 1024; i += 128) {
        ((float4*)sW0)[i] = ((const float4*)wp0)[i];
        ((float4*)sW1)[i] = ((const float4*)wp1)[i];
    }
    const float4* src = (const float4*)feat + blockIdx.x * 1024;
#pragma unroll
    for (int jj = 0; jj < 8; jj++) {
        int idx = t + jj * 128;
        float4 v = src[idx];
        int d = idx * 4, r = d >> 6, k0 = d & 63;
        sAt[(k0 + 0) * 68 + r] = v.x;
        sAt[(k0 + 1) * 68 + r] = v.y;
        sAt[(k0 + 2) * 68 + r] = v.z;
        sAt[(k0 + 3) * 68 + r] = v.w;
    }
    __syncthreads();
    int w = t >> 5, c0 = (t & 31) * 2;
    int r0 = w * 16;
    u64 acc[16];
#pragma unroll
    for (int j = 0; j < 16; j++) acc[j] = pk2(0.f, 0.f);
#pragma unroll 4
    for (int k = 0; k < 64; k++) {
        const float* ar = sAt + k * 68 + r0;
        float4 a0 = *(const float4*)(ar);
        float4 a1 = *(const float4*)(ar + 4);
        float4 a2 = *(const float4*)(ar + 8);
        float4 a3 = *(const float4*)(ar + 12);
        u64 w0 = *(const u64*)(sW0 + k * 64 + c0);
        u64 w1 = *(const u64*)(sW1 + k * 64 + c0);
        acc[0]  = fma2_(pk2(a0.x, a0.x), w0, acc[0]);
        acc[1]  = fma2_(pk2(a0.y, a0.y), w1, acc[1]);
        acc[2]  = fma2_(pk2(a0.z, a0.z), w1, acc[2]);
        acc[3]  = fma2_(pk2(a0.w, a0.w), w1, acc[3]);
        acc[4]  = fma2_(pk2(a1.x, a1.x), w0, acc[4]);
        acc[5]  = fma2_(pk2(a1.y, a1.y), w1, acc[5]);
        acc[6]  = fma2_(pk2(a1.z, a1.z), w1, acc[6]);
        acc[7]  = fma2_(pk2(a1.w, a1.w), w1, acc[7]);
        acc[8]  = fma2_(pk2(a2.x, a2.x), w0, acc[8]);
        acc[9]  = fma2_(pk2(a2.y, a2.y), w1, acc[9]);
        acc[10] = fma2_(pk2(a2.z, a2.z), w1, acc[10]);
        acc[11] = fma2_(pk2(a2.w, a2.w), w1, acc[11]);
        acc[12] = fma2_(pk2(a3.x, a3.x), w0, acc[12]);
        acc[13] = fma2_(pk2(a3.y, a3.y), w1, acc[13]);
        acc[14] = fma2_(pk2(a3.z, a3.z), w1, acc[14]);
        acc[15] = fma2_(pk2(a3.w, a3.w), w1, acc[15]);
    }
#pragma unroll
    for (int j = 0; j < 16; j++) {
        int row = r0 + j;
        int node = blockIdx.x * 16 + (row >> 2);
        *(u64*)(g_pre + node * 256 + (row & 3) * 64 + c0) = acc[j];
    }
#if __CUDA_ARCH__ >= 900
    cudaTriggerProgrammaticLaunchCompletion();
#endif
}

// ============================================================
// K2: fused edge kernel (filters + coupling). warp = node.
//     4 warps/block (128 thr), grid 1024 (R15 proven shape).
// ============================================================
#define KE_WARPS 4
#define KE_PW (576 + 272 + 128)  // sRB[16][36] + sH[4][68] + s_u[32]f4
#define KE_SMEM ((1024 + 4096 + KE_WARPS * KE_PW) * 4)

#define COUPLE(UE, A0, AY, AZ, AX, F) do { \
    float fa, fb; upk2(F, fa, fb); \
    float uy = UE.x, uz = UE.y, ux = UE.z; \
    float sa = AY.x * uy + AZ.x * uz + AX.x * ux; \
    float sb = AY.y * uy + AZ.y * uz + AX.y * ux; \
    float t0a = A0.x * fa, t0b = A0.y * fb; \
    S0a += t0a;       S0b += t0b; \
    S1a += sa * fa;   S1b += sb * fb; \
    U0a += uy * t0a;  U0b += uy * t0b; \
    U1a += uz * t0a;  U1b += uz * t0b; \
    U2a += ux * t0a;  U2b += ux * t0b; \
    P0a += AY.x * fa; P0b += AY.y * fb; \
    P1a += AZ.x * fa; P1b += AZ.y * fb; \
    P2a += AX.x * fa; P2b += AX.y * fb; \
    float cya = AZ.x * ux - AX.x * uz, cyb = AZ.y * ux - AX.y * uz; \
    float cza = AX.x * uy - AY.x * ux, czb = AX.y * uy - AY.y * ux; \
    float cxa = AY.x * uz - AZ.x * uy, cxb = AY.y * uz - AZ.y * uy; \
    Q0a += cya * fa;  Q0b += cyb * fb; \
    Q1a += cza * fa;  Q1b += czb * fb; \
    Q2a += cxa * fa;  Q2b += cxb * fb; \
} while (0)

__global__ void __launch_bounds__(128) k_edge(const float* __restrict__ xyz,
                                              const float* __restrict__ wf1,
                                              const float* __restrict__ wf2,
                                              const int* __restrict__ src,
                                              const int* __restrict__ emask) {
    extern __shared__ float sm[];
    float* sW1 = sm;         // wf1 [16][64]
    float* sW2 = sm + 1024;  // wf2 [64][64]
    int t = threadIdx.x, w = t >> 5, lane = t & 31;
    for (int i = t; i < 256; i += 128) ((float4*)sW1)[i] = ((const float4*)wf1)[i];
    for (int i = t; i < 1024; i += 128) ((float4*)sW2)[i] = ((const float4*)wf2)[i];
    float* base = sm + 5120 + w * KE_PW;
    float* sRB = base;                   // [q16][36]
    float* sH = base + 576;              // [e4][68]
    float4* s_u = (float4*)(base + 848); // [32] (uy,uz,ux,j)
    __syncthreads();

    int node = blockIdx.x * KE_WARPS + w;
    // ---- phase A: lane = edge (inputs only; overlaps with k_pre via PDL) ----
    s_u[lane] = make_float4(0.f, 0.f, 0.f, __int_as_float(node));
    __syncwarp();
    int eid = node * MM + lane;
    int mk = emask[eid];
    int j = src[eid];
    float nx = xyz[node * 3], ny = xyz[node * 3 + 1], nz = xyz[node * 3 + 2];
    float rx = xyz[j * 3] - nx, ry = xyz[j * 3 + 1] - ny, rz = xyz[j * 3 + 2] - nz;
    float d2 = rx * rx + ry * ry + rz * rz;
    float invd = rsqrtf(d2);
    float x = d2 * invd * 0.2f;
    bool act = (mk != 0) && (x < 1.f);
    unsigned actmask = __ballot_sync(0xffffffffu, act);
    int nact = __popc(actmask);
    int rank = __popc(actmask & ((1u << lane) - 1u));
    if (act) {
        float x3 = x * x * x;
        float env = 1.f + x3 * (-10.f + x * (15.f - 6.f * x));
        float scale = env * invd;
        s_u[rank] = make_float4(ry * invd, rz * invd, rx * invd, __int_as_float(j));
#pragma unroll
        for (int q = 0; q < 16; q++) sRB[q * 36 + rank] = __sinf(x * (float)q) * scale;
    }
    __syncwarp();

#if __CUDA_ARCH__ >= 900
    cudaGridDependencySynchronize();   // g_pre must be complete past this point
#endif

    // ---- phase B: 4-edge tiles; lane = channel pair c0 ----
    int c0 = lane * 2;
    float S0a = 0, S0b = 0, S1a = 0, S1b = 0;
    float U0a = 0, U0b = 0, U1a = 0, U1b = 0, U2a = 0, U2b = 0;
    float P0a = 0, P0b = 0, P1a = 0, P1b = 0, P2a = 0, P2b = 0;
    float Q0a = 0, Q0b = 0, Q1a = 0, Q1b = 0, Q2a = 0, Q2b = 0;

    for (int r0 = 0; r0 < nact; r0 += 4) {
        float4 ue0 = s_u[r0], ue1 = s_u[r0 + 1], ue2 = s_u[r0 + 2], ue3 = s_u[r0 + 3];
        const float* p0 = g_pre + __float_as_int(ue0.w) * 256 + c0;
        const float* p1 = g_pre + __float_as_int(ue1.w) * 256 + c0;
        const float* p2 = g_pre + __float_as_int(ue2.w) * 256 + c0;
        const float* p3 = g_pre + __float_as_int(ue3.w) * 256 + c0;
        float2 A00 = *(const float2*)(p0), A0y = *(const float2*)(p0 + 64),
               A0z = *(const float2*)(p0 + 128), A0x = *(const float2*)(p0 + 192);
        float2 B00 = *(const float2*)(p1), B0y = *(const float2*)(p1 + 64),
               B0z = *(const float2*)(p1 + 128), B0x = *(const float2*)(p1 + 192);
        float2 C00 = *(const float2*)(p2), C0y = *(const float2*)(p2 + 64),
               C0z = *(const float2*)(p2 + 128), C0x = *(const float2*)(p2 + 192);
        float2 D00 = *(const float2*)(p3), D0y = *(const float2*)(p3 + 64),
               D0z = *(const float2*)(p3 + 128), D0x = *(const float2*)(p3 + 192);

        u64 H0 = pk2(0.f, 0.f), H1 = H0, H2 = H0, H3 = H0;
#pragma unroll
        for (int q = 0; q < 16; q++) {
            float4 rb = *(const float4*)(sRB + q * 36 + r0);
            u64 wv = *(const u64*)(sW1 + q * 64 + c0);
            H0 = fma2_(pk2(rb.x, rb.x), wv, H0);
            H1 = fma2_(pk2(rb.y, rb.y), wv, H1);
            H2 = fma2_(pk2(rb.z, rb.z), wv, H2);
            H3 = fma2_(pk2(rb.w, rb.w), wv, H3);
        }
        {
            float a, b;
            upk2(H0, a, b); *(u64*)(sH + 0 * 68 + c0) = pk2(ssp(a), ssp(b));
            upk2(H1, a, b); *(u64*)(sH + 1 * 68 + c0) = pk2(ssp(a), ssp(b));
            upk2(H2, a, b); *(u64*)(sH + 2 * 68 + c0) = pk2(ssp(a), ssp(b));
            upk2(H3, a, b); *(u64*)(sH + 3 * 68 + c0) = pk2(ssp(a), ssp(b));
        }
        __syncwarp();

        u64 F0 = pk2(0.f, 0.f), F1 = F0, F2 = F0, F3 = F0;
#pragma unroll 4
        for (int kk = 0; kk < 64; kk += 4) {
            float4 h0 = *(const float4*)(sH + 0 * 68 + kk);
            float4 h1 = *(const float4*)(sH + 1 * 68 + kk);
            float4 h2 = *(const float4*)(sH + 2 * 68 + kk);
            float4 h3 = *(const float4*)(sH + 3 * 68 + kk);
            u64 w0 = *(const u64*)(sW2 + (kk + 0) * 64 + c0);
            u64 w1 = *(const u64*)(sW2 + (kk + 1) * 64 + c0);
            u64 w2 = *(const u64*)(sW2 + (kk + 2) * 64 + c0);
            u64 w3 = *(const u64*)(sW2 + (kk + 3) * 64 + c0);
            F0 = fma2_(pk2(h0.x, h0.x), w0, F0);
            F1 = fma2_(pk2(h1.x, h1.x), w0, F1);
            F2 = fma2_(pk2(h2.x, h2.x), w0, F2);
            F3 = fma2_(pk2(h3.x, h3.x), w0, F3);
            F0 = fma2_(pk2(h0.y, h0.y), w1, F0);
            F1 = fma2_(pk2(h1.y, h1.y), w1, F1);
            F2 = fma2_(pk2(h2.y, h2.y), w1, F2);
            F3 = fma2_(pk2(h3.y, h3.y), w1, F3);
            F0 = fma2_(pk2(h0.z, h0.z), w2, F0);
            F1 = fma2_(pk2(h1.z, h1.z), w2, F1);
            F2 = fma2_(pk2(h2.z, h2.z), w2, F2);
            F3 = fma2_(pk2(h3.z, h3.z), w2, F3);
            F0 = fma2_(pk2(h0.w, h0.w), w3, F0);
            F1 = fma2_(pk2(h1.w, h1.w), w3, F1);
            F2 = fma2_(pk2(h2.w, h2.w), w3, F2);
            F3 = fma2_(pk2(h3.w, h3.w), w3, F3);
        }
        if (r0 + 1 >= nact) F1 = pk2(0.f, 0.f);
        if (r0 + 2 >= nact) F2 = pk2(0.f, 0.f);
        if (r0 + 3 >= nact) F3 = pk2(0.f, 0.f);

        COUPLE(ue0, A00, A0y, A0z, A0x, F0);
        COUPLE(ue1, B00, B0y, B0z, B0x, F1);
        COUPLE(ue2, C00, C0y, C0z, C0x, F2);
        COUPLE(ue3, D00, D0y, D0z, D0x, F3);
        __syncwarp();
    }

    float* dst = g_acc + node * 704 + c0;
    *(float2*)(dst + 0)   = make_float2(S0a, S0b);
    *(float2*)(dst + 64)  = make_float2(S1a, S1b);
    *(float2*)(dst + 128) = make_float2(U0a, U0b);
    *(float2*)(dst + 192) = make_float2(U1a, U1b);
    *(float2*)(dst + 256) = make_float2(U2a, U2b);
    *(float2*)(dst + 320) = make_float2(P0a, P0b);
    *(float2*)(dst + 384) = make_float2(P1a, P1b);
    *(float2*)(dst + 448) = make_float2(P2a, P2b);
    *(float2*)(dst + 512) = make_float2(Q0a, Q0b);
    *(float2*)(dst + 576) = make_float2(Q1a, Q1b);
    *(float2*)(dst + 640) = make_float2(Q2a, Q2b);
#if __CUDA_ARCH__ >= 900
    cudaTriggerProgrammaticLaunchCompletion();
#endif
}

// ============================================================
// K3: combined w_a GEMMs + fused gate (R16). g_agg stores gated values.
// ============================================================
#define KAG_SMEM (12288 * 4)
__global__ void __launch_bounds__(256) k_ag(const float* __restrict__ wa0,
                                            const float* __restrict__ wa1) {
    extern __shared__ float sW[];
    int t = threadIdx.x, w = t >> 5, c0 = (t & 31) * 2;
    if (blockIdx.x < 256) {
        for (int i = t; i < 2048; i += 256) ((float4*)sW)[i] = ((const float4*)wa0)[i];
#if __CUDA_ARCH__ >= 900
        cudaGridDependencySynchronize();
#endif
        __syncthreads();
        int n0 = blockIdx.x * 16 + w * 2;
        const float* A = g_acc + n0 * 704;
        const float* B = A + 704;
        u64 e0 = pk2(0.f, 0.f), e1 = e0, f0 = e0, f1 = e0;
#pragma unroll 4
        for (int kk = 0; kk < 64; kk += 4) {
            float4 a = *(const float4*)(A + kk);
            float4 a2 = *(const float4*)(A + 64 + kk);
            float4 b = *(const float4*)(B + kk);
            float4 b2 = *(const float4*)(B + 64 + kk);
            u64 w0 = *(const u64*)(sW + (kk + 0) * 64 + c0);
            u64 v0 = *(const u64*)(sW + (64 + kk + 0) * 64 + c0);
            u64 w1 = *(const u64*)(sW + (kk + 1) * 64 + c0);
            u64 v1 = *(const u64*)(sW + (64 + kk + 1) * 64 + c0);
            u64 w2 = *(const u64*)(sW + (kk + 2) * 64 + c0);
            u64 v2 = *(const u64*)(sW + (64 + kk + 2) * 64 + c0);
            u64 w3 = *(const u64*)(sW + (kk + 3) * 64 + c0);
            u64 v3 = *(const u64*)(sW + (64 + kk + 3) * 64 + c0);
            e0 = fma2_(pk2(a.x, a.x), w0, e0);
            f0 = fma2_(pk2(b.x, b.x), w0, f0);
            e1 = fma2_(pk2(a2.x, a2.x), v0, e1);
            f1 = fma2_(pk2(b2.x, b2.x), v0, f1);
            e0 = fma2_(pk2(a.y, a.y), w1, e0);
            f0 = fma2_(pk2(b.y, b.y), w1, f0);
            e1 = fma2_(pk2(a2.y, a2.y), v1, e1);
            f1 = fma2_(pk2(b2.y, b2.y), v1, f1);
            e0 = fma2_(pk2(a.z, a.z), w2, e0);
            f0 = fma2_(pk2(b.z, b.z), w2, f0);
            e1 = fma2_(pk2(a2.z, a2.z), v2, e1);
            f1 = fma2_(pk2(b2.z, b2.z), v2, f1);
            e0 = fma2_(pk2(a.w, a.w), w3, e0);
            f0 = fma2_(pk2(b.w, b.w), w3, f0);
            e1 = fma2_(pk2(a2.w, a2.w), v3, e1);
            f1 = fma2_(pk2(b2.w, b2.w), v3, f1);
        }
        float xa, xb, ya, yb;
        upk2(e0, xa, xb); upk2(e1, ya, yb);
        float s0 = xa + ya, s1 = xb + yb;
        *(float2*)(g_agg + n0 * 256 + c0) = make_float2(s0 * ssp(s0), s1 * ssp(s1));
        upk2(f0, xa, xb); upk2(f1, ya, yb);
        s0 = xa + ya; s1 = xb + yb;
        *(float2*)(g_agg + (n0 + 1) * 256 + c0) = make_float2(s0 * ssp(s0), s1 * ssp(s1));
    } else {
        for (int i = t; i < 3072; i += 256) ((float4*)sW)[i] = ((const float4*)wa1)[i];
#if __CUDA_ARCH__ >= 900
        cudaGridDependencySynchronize();
#endif
        __syncthreads();
        int n0 = (blockIdx.x - 256) * 16 + w * 2;
        u64 m0 = pk2(0.f, 0.f), m1 = m0, m2 = m0;
        u64 q0 = m0, q1 = m0, q2 = m0;
#pragma unroll
        for (int s = 0; s < 3; s++) {
            const float* As = g_acc + n0 * 704 + 128 + s * 192;
            const float* Bs = As + 704;
            const float* ws = sW + s * 4096;
#pragma unroll 2
            for (int kk = 0; kk < 64; kk += 4) {
                float4 a0 = *(const float4*)(As + kk);
                float4 a1 = *(const float4*)(As + 64 + kk);
                float4 a2 = *(const float4*)(As + 128 + kk);
                float4 b0 = *(const float4*)(Bs + kk);
                float4 b1 = *(const float4*)(Bs + 64 + kk);
                float4 b2 = *(const float4*)(Bs + 128 + kk);
                u64 w0 = *(const u64*)(ws + (kk + 0) * 64 + c0);
                u64 w1 = *(const u64*)(ws + (kk + 1) * 64 + c0);
                u64 w2 = *(const u64*)(ws + (kk + 2) * 64 + c0);
                u64 w3 = *(const u64*)(ws + (kk + 3) * 64 + c0);
                m0 = fma2_(pk2(a0.x, a0.x), w0, m0);
                q0 = fma2_(pk2(b0.x, b0.x), w0, q0);
                m1 = fma2_(pk2(a1.x, a1.x), w0, m1);
                q1 = fma2_(pk2(b1.x, b1.x), w0, q1);
                m2 = fma2_(pk2(a2.x, a2.x), w0, m2);
                q2 = fma2_(pk2(b2.x, b2.x), w0, q2);
                m0 = fma2_(pk2(a0.y, a0.y), w1, m0);
                q0 = fma2_(pk2(b0.y, b0.y), w1, q0);
                m1 = fma2_(pk2(a1.y, a1.y), w1, m1);
                q1 = fma2_(pk2(b1.y, b1.y), w1, q1);
                m2 = fma2_(pk2(a2.y, a2.y), w1, m2);
                q2 = fma2_(pk2(b2.y, b2.y), w1, q2);
                m0 = fma2_(pk2(a0.z, a0.z), w2, m0);
                q0 = fma2_(pk2(b0.z, b0.z), w2, q0);
                m1 = fma2_(pk2(a1.z, a1.z), w2, m1);
                q1 = fma2_(pk2(b1.z, b1.z), w2, q1);
                m2 = fma2_(pk2(a2.z, a2.z), w2, m2);
                q2 = fma2_(pk2(b2.z, b2.z), w2, q2);
                m0 = fma2_(pk2(a0.w, a0.w), w3, m0);
                q0 = fma2_(pk2(b0.w, b0.w), w3, q0);
                m1 = fma2_(pk2(a1.w, a1.w), w3, m1);
                q1 = fma2_(pk2(b1.w, b1.w), w3, q1);
                m2 = fma2_(pk2(a2.w, a2.w), w3, m2);
                q2 = fma2_(pk2(b2.w, b2.w), w3, q2);
            }
        }
        {
            float m0a, m0b, m1a, m1b, m2a, m2b;
            upk2(m0, m0a, m0b); upk2(m1, m1a, m1b); upk2(m2, m2a, m2b);
            float ga = ssp(sqrtf(m0a * m0a + m1a * m1a + m2a * m2a + 1e-12f));
            float gb = ssp(sqrtf(m0b * m0b + m1b * m1b + m2b * m2b + 1e-12f));
            *(float2*)(g_agg + n0 * 256 + 64 + c0) = make_float2(m0a * ga, m0b * gb);
            *(float2*)(g_agg + n0 * 256 + 128 + c0) = make_float2(m1a * ga, m1b * gb);
            *(float2*)(g_agg + n0 * 256 + 192 + c0) = make_float2(m2a * ga, m2b * gb);
        }
        {
            float m0a, m0b, m1a, m1b, m2a, m2b;
            upk2(q0, m0a, m0b); upk2(q1, m1a, m1b); upk2(q2, m2a, m2b);
            float ga = ssp(sqrtf(m0a * m0a + m1a * m1a + m2a * m2a + 1e-12f));
            float gb = ssp(sqrtf(m0b * m0b + m1b * m1b + m2b * m2b + 1e-12f));
            *(float2*)(g_agg + (n0 + 1) * 256 + 64 + c0) = make_float2(m0a * ga, m0b * gb);
            *(float2*)(g_agg + (n0 + 1) * 256 + 128 + c0) = make_float2(m1a * ga, m1b * gb);
            *(float2*)(g_agg + (n0 + 1) * 256 + 192 + c0) = make_float2(m2a * ga, m2b * gb);
        }
    }
#if __CUDA_ARCH__ >= 900
    cudaTriggerProgrammaticLaunchCompletion();
#endif
}

// ============================================================
// K4: w_b ielin + residual on pre-gated g_agg. 16 nodes/block, 128 thr,
//     grid 256. Same balanced 16-row warp tile as k_pre.
// ============================================================
#define KFN_SMEM ((8192 + 64 * 68) * 4)
__global__ void __launch_bounds__(128) k_fin(const float* __restrict__ feat,
                                             const float* __restrict__ wb0,
                                             const float* __restrict__ wb1,
                                             float* __restrict__ out) {
    extern __shared__ float sm[];
    float* sW0 = sm;
    float* sW1 = sm + 4096;
    float* sAt = sm + 8192;   // [k64][row64], stride 68
    int t = threadIdx.x;
    for (int i = t; i < 1024; i += 128) {
        ((float4*)sW0)[i] = ((const float4*)wb0)[i];
        ((float4*)sW1)[i] = ((const float4*)wb1)[i];
    }
#if __CUDA_ARCH__ >= 900
    cudaGridDependencySynchronize();   // g_agg ready past this point
#endif
    const float4* src = (const float4*)g_agg + blockIdx.x * 1024;
#pragma unroll
    for (int jj = 0; jj < 8; jj++) {
        int idx = t + jj * 128;
        float4 v = src[idx];
        int d = idx * 4, r = d >> 6, k0 = d & 63;
        sAt[(k0 + 0) * 68 + r] = v.x;
        sAt[(k0 + 1) * 68 + r] = v.y;
        sAt[(k0 + 2) * 68 + r] = v.z;
        sAt[(k0 + 3) * 68 + r] = v.w;
    }
    __syncthreads();
    int w = t >> 5, c0 = (t & 31) * 2;
    int r0 = w * 16;
    u64 acc[16];
#pragma unroll
    for (int j = 0; j < 16; j++) acc[j] = pk2(0.f, 0.f);
#pragma unroll 4
    for (int k = 0; k < 64; k++) {
        const float* ar = sAt + k * 68 + r0;
        float4 a0 = *(const float4*)(ar);
        float4 a1 = *(const float4*)(ar + 4);
        float4 a2 = *(const float4*)(ar + 8);
        float4 a3 = *(const float4*)(ar + 12);
        u64 w0 = *(const u64*)(sW0 + k * 64 + c0);
        u64 w1 = *(const u64*)(sW1 + k * 64 + c0);
        acc[0]  = fma2_(pk2(a0.x, a0.x), w0, acc[0]);
        acc[1]  = fma2_(pk2(a0.y, a0.y), w1, acc[1]);
        acc[2]  = fma2_(pk2(a0.z, a0.z), w1, acc[2]);
        acc[3]  = fma2_(pk2(a0.w, a0.w), w1, acc[3]);
        acc[4]  = fma2_(pk2(a1.x, a1.x), w0, acc[4]);
        acc[5]  = fma2_(pk2(a1.y, a1.y), w1, acc[5]);
        acc[6]  = fma2_(pk2(a1.z, a1.z), w1, acc[6]);
        acc[7]  = fma2_(pk2(a1.w, a1.w), w1, acc[7]);
        acc[8]  = fma2_(pk2(a2.x, a2.x), w0, acc[8]);
        acc[9]  = fma2_(pk2(a2.y, a2.y), w1, acc[9]);
        acc[10] = fma2_(pk2(a2.z, a2.z), w1, acc[10]);
        acc[11] = fma2_(pk2(a2.w, a2.w), w1, acc[11]);
        acc[12] = fma2_(pk2(a3.x, a3.x), w0, acc[12]);
        acc[13] = fma2_(pk2(a3.y, a3.y), w1, acc[13]);
        acc[14] = fma2_(pk2(a3.z, a3.z), w1, acc[14]);
        acc[15] = fma2_(pk2(a3.w, a3.w), w1, acc[15]);
    }
#pragma unroll
    for (int j = 0; j < 16; j++) {
        int row = r0 + j;
        int node = blockIdx.x * 16 + (row >> 2);
        int idx = node * 256 + (row & 3) * 64 + c0;
        float2 fv = *(const float2*)(feat + idx);
        float oa, ob;
        upk2(acc[j], oa, ob);
        *(float2*)(out + idx) = make_float2(fv.x + oa, fv.y + ob);
    }
}

// ============================================================
template <typename... Args>
static void launch_pdl(void (*kern)(Args...), int grid, int block, int smem, Args... args) {
    cudaLaunchConfig_t cfg = {};
    cfg.gridDim = dim3(grid, 1, 1);
    cfg.blockDim = dim3(block, 1, 1);
    cfg.dynamicSmemBytes = (size_t)smem;
    cfg.stream = 0;
    cudaLaunchAttribute attr[1];
    attr[0].id = cudaLaunchAttributeProgrammaticStreamSerialization;
    attr[0].val.programmaticStreamSerializationAllowed = 1;
    cfg.attrs = attr;
    cfg.numAttrs = 1;
    cudaLaunchKernelEx(&cfg, kern, args...);
}

extern "C" void kernel_launch(void* const* d_in, const int* in_sizes, int n_in,
                              void* d_out, int out_size) {
    const float* xyz = (const float*)d_in[0];
    const float* feat = (const float*)d_in[1];
    const float* wf1 = (const float*)d_in[2];
    const float* wf2 = (const float*)d_in[3];
    const float* wp0 = (const float*)d_in[4];
    const float* wp1 = (const float*)d_in[5];
    const float* wa0 = (const float*)d_in[6];
    const float* wa1 = (const float*)d_in[7];
    const float* wb0 = (const float*)d_in[8];
    const float* wb1 = (const float*)d_in[9];
    const int* src = (const int*)d_in[10];
    const int* emask = (const int*)d_in[11];
    float* out = (float*)d_out;

    cudaFuncSetAttribute(k_pre, cudaFuncAttributeMaxDynamicSharedMemorySize, KP_SMEM);
    cudaFuncSetAttribute(k_edge, cudaFuncAttributeMaxDynamicSharedMemorySize, KE_SMEM);
    cudaFuncSetAttribute(k_ag, cudaFuncAttributeMaxDynamicSharedMemorySize, KAG_SMEM);
    cudaFuncSetAttribute(k_fin, cudaFuncAttributeMaxDynamicSharedMemorySize, KFN_SMEM);

    k_pre<<<256, 128, KP_SMEM>>>(feat, wp0, wp1);
    launch_pdl(k_edge, NN / KE_WARPS, 128, KE_SMEM, xyz, wf1, wf2, src, emask);
    launch_pdl(k_ag, 512, 256, KAG_SMEM, wa0, wa1);
    launch_pdl(k_fin, 256, 128, KFN_SMEM, feat, wb0, wb1, out);
}